// round 16
// baseline (speedup 1.0000x reference)
#include <cuda_runtime.h>

#define NB   32
#define CIN  64
#define COUT 128
#define HW   4096               // 64*64 spatial floats per (n,ci)
#define INV_OHW (1.0f/4489.0f)  // 1/(67*67)

#define ROWS_PER_BLK 2
#define NXB  (NB * CIN / ROWS_PER_BLK)   // 1024 x-blocks
#define NWB  CIN                          // 64 w-blocks
#define GRID (NXB + NWB)                  // 1088: single wave

__device__ float g_Sx[NB * CIN];
__device__ float g_Sw[CIN * COUT];

__device__ __forceinline__ float warp_sum(float v) {
    v += __shfl_xor_sync(0xffffffffu, v, 16);
    v += __shfl_xor_sync(0xffffffffu, v, 8);
    v += __shfl_xor_sync(0xffffffffu, v, 4);
    v += __shfl_xor_sync(0xffffffffu, v, 2);
    v += __shfl_xor_sync(0xffffffffu, v, 1);
    return v;
}
__device__ __forceinline__ float warp_max(float v) {
    v = fmaxf(v, __shfl_xor_sync(0xffffffffu, v, 16));
    v = fmaxf(v, __shfl_xor_sync(0xffffffffu, v, 8));
    v = fmaxf(v, __shfl_xor_sync(0xffffffffu, v, 4));
    v = fmaxf(v, __shfl_xor_sync(0xffffffffu, v, 2));
    v = fmaxf(v, __shfl_xor_sync(0xffffffffu, v, 1));
    return v;
}

// Streaming (evict-first) 128-bit load: x is touched exactly once, so don't
// let it pollute L1/L2 (the only cached state that matters is g_Sw + g_Sx).
__device__ __forceinline__ float4 ldcs4(const float4* p) {
    return __ldcs(p);
}

// Kernel 1: bandwidth-shaped reduction.
// x-block: 2 rows (32KB), 256 threads, 8 independent streaming LDG.128.
__global__ void __launch_bounds__(256) reduce_kernel(
    const float* __restrict__ x,
    const float* __restrict__ w)
{
    const int b = blockIdx.x;
    const int t = threadIdx.x;
    const int lane = t & 31;
    const int wid  = t >> 5;

    if (b < NXB) {
        const float4* p = reinterpret_cast<const float4*>(x)
                        + (size_t)b * (ROWS_PER_BLK * HW / 4);
        float4 v0 = ldcs4(p + t);
        float4 v1 = ldcs4(p + t + 256);
        float4 v2 = ldcs4(p + t + 512);
        float4 v3 = ldcs4(p + t + 768);
        float4 v4 = ldcs4(p + t + 1024);
        float4 v5 = ldcs4(p + t + 1280);
        float4 v6 = ldcs4(p + t + 1536);
        float4 v7 = ldcs4(p + t + 1792);

        float s0 = ((v0.x + v0.y) + (v0.z + v0.w))
                 + ((v1.x + v1.y) + (v1.z + v1.w))
                 + ((v2.x + v2.y) + (v2.z + v2.w))
                 + ((v3.x + v3.y) + (v3.z + v3.w));
        float s1 = ((v4.x + v4.y) + (v4.z + v4.w))
                 + ((v5.x + v5.y) + (v5.z + v5.w))
                 + ((v6.x + v6.y) + (v6.z + v6.w))
                 + ((v7.x + v7.y) + (v7.z + v7.w));

        s0 = warp_sum(s0);
        s1 = warp_sum(s1);

        __shared__ float sh0[8], sh1[8];
        if (lane == 0) { sh0[wid] = s0; sh1[wid] = s1; }
        __syncthreads();
        if (t == 0) {
            float u0 = ((sh0[0] + sh0[1]) + (sh0[2] + sh0[3]))
                     + ((sh0[4] + sh0[5]) + (sh0[6] + sh0[7]));
            float u1 = ((sh1[0] + sh1[1]) + (sh1[2] + sh1[3]))
                     + ((sh1[4] + sh1[5]) + (sh1[6] + sh1[7]));
            g_Sx[b * 2]     = u0;
            g_Sx[b * 2 + 1] = u1;
        }
    } else {
        // w-block: one per ci, thread co sums its 16 contiguous taps.
        // Normal cache policy — g_Sw/K2 benefit from L2 residency.
        const int ci = b - NXB;
        if (t < COUT) {
            const float4* p = reinterpret_cast<const float4*>(w)
                            + ((size_t)ci * COUT + t) * 4;
            float4 a0 = p[0], a1 = p[1], a2 = p[2], a3 = p[3];
            g_Sw[ci * COUT + t] =
                ((a0.x + a0.y) + (a0.z + a0.w)) +
                ((a1.x + a1.y) + (a1.z + a1.w)) +
                ((a2.x + a2.y) + (a2.z + a2.w)) +
                ((a3.x + a3.y) + (a3.z + a3.w));
        }
    }
}

// Kernel 2: one block per n, 128 threads (one per co).
__global__ void __launch_bounds__(COUT) finalize_kernel(
    const float* __restrict__ cb,
    const float* __restrict__ eb,
    float* __restrict__ out)
{
    const int n  = blockIdx.x;
    const int co = threadIdx.x;
    const int lane = co & 31;
    const int wid  = co >> 5;

    __shared__ float sx[CIN];
    if (co < CIN) sx[co] = g_Sx[n * CIN + co];
    __syncthreads();

    float a0 = 0.f, a1 = 0.f, a2 = 0.f, a3 = 0.f;
    #pragma unroll
    for (int ci = 0; ci < CIN; ci += 4) {
        a0 = fmaf(sx[ci + 0], g_Sw[(ci + 0) * COUT + co], a0);
        a1 = fmaf(sx[ci + 1], g_Sw[(ci + 1) * COUT + co], a1);
        a2 = fmaf(sx[ci + 2], g_Sw[(ci + 2) * COUT + co], a2);
        a3 = fmaf(sx[ci + 3], g_Sw[(ci + 3) * COUT + co], a3);
    }
    const float pooled = ((a0 + a1) + (a2 + a3)) * INV_OHW + cb[co] + eb[co];

    __shared__ float red[4], red2[4];
    float m = warp_max(pooled);
    if (lane == 0) red[wid] = m;
    __syncthreads();
    const float m0 = fmaxf(fmaxf(red[0], red[1]), fmaxf(red[2], red[3]));

    float e = warp_sum(__expf(pooled - m0));
    if (lane == 0) red2[wid] = e;
    __syncthreads();
    if (co == 0) {
        float tot = (red2[0] + red2[1]) + (red2[2] + red2[3]);
        out[n] = 10.0f * (m0 + logf(tot));
    }
}

extern "C" void kernel_launch(void* const* d_in, const int* in_sizes, int n_in,
                              void* d_out, int out_size) {
    const float* x  = (const float*)d_in[0];   // (32,64,64,64)
    const float* w  = (const float*)d_in[1];   // (64,128,4,4)
    const float* cb = (const float*)d_in[2];   // (128,)
    const float* eb = (const float*)d_in[3];   // (128,)
    float* out = (float*)d_out;                // (32,1)

    reduce_kernel<<<GRID, 256>>>(x, w);
    finalize_kernel<<<NB, COUT>>>(cb, eb, out);
}